// round 17
// baseline (speedup 1.0000x reference)
#include <cuda_runtime.h>

#define BATCH   8
#define NPTS    4096
#define NPOINTS 1024
#define NSAMPLE 32
#define PIN_A   68
#define PIN_B   132
#define NW_PER_B 17                    // worker blocks per batch
#define NWORKERS (NW_PER_B * BATCH)    // 136
#define NBLOCKS  (BATCH + NWORKERS)    // 144 <= 148 SMs -> all resident wave 1
#define NGRP     4
#define THREADS  512

#define SXYZ_F   (NPTS * 3)                    // 12288 floats
#define GRP_F    (32 * PIN_A + 32 * PIN_B)     // 6400 floats per group
#define SMEM_DYN ((SXYZ_F + NGRP * GRP_F) * 4 + NGRP * 32 * 4 + NGRP * 4 * 4)

// packed centroid+flag: {x, y, z, bits(t+1)}. One 16B STG publishes payload+flag.
__device__ float4 g_cent[BATCH * NPOINTS];

// ---------------------------------------------------------------------------
__device__ __forceinline__ float sqd_nofma(float x, float y, float z,
                                           float cx, float cy, float cz) {
    float dx = x - cx, dy = y - cy, dz = z - cz;
    return __fadd_rn(__fadd_rn(__fmul_rn(dx, dx), __fmul_rn(dy, dy)), __fmul_rn(dz, dz));
}

__device__ __forceinline__ unsigned long long f2_add(unsigned long long a, unsigned long long b) {
    unsigned long long r;
    asm("add.rn.f32x2 %0, %1, %2;" : "=l"(r) : "l"(a), "l"(b));
    return r;
}
__device__ __forceinline__ unsigned long long f2_mul(unsigned long long a, unsigned long long b) {
    unsigned long long r;
    asm("mul.rn.f32x2 %0, %1, %2;" : "=l"(r) : "l"(a), "l"(b));
    return r;
}
__device__ __forceinline__ unsigned long long f2_pack(float lo, float hi) {
    unsigned long long r;
    asm("mov.b64 %0, {%1, %2};" : "=l"(r) : "f"(lo), "f"(hi));
    return r;
}
__device__ __forceinline__ void f2_unpack(unsigned long long v, float& lo, float& hi) {
    asm("mov.b64 {%0, %1}, %2;" : "=f"(lo), "=f"(hi) : "l"(v));
}

__device__ __forceinline__ float4 ldcg_v4(const float4* p) {
    float4 v;
    asm volatile("ld.global.cg.v4.f32 {%0,%1,%2,%3}, [%4];"
                 : "=f"(v.x), "=f"(v.y), "=f"(v.z), "=f"(v.w) : "l"(p) : "memory");
    return v;
}
__device__ __forceinline__ void stcg_v4(float4* p, float x, float y, float z, float w) {
    asm volatile("st.global.cg.v4.f32 [%0], {%1,%2,%3,%4};"
                 :: "l"(p), "f"(x), "f"(y), "f"(z), "f"(w) : "memory");
}

__device__ __forceinline__ void bar_grp(int id) {
    asm volatile("bar.sync %0, 128;" :: "r"(id) : "memory");
}

__device__ __forceinline__ int spread3(int v) {
    return (v & 1) | ((v & 2) << 2) | ((v & 4) << 4);
}

// ---------------------------------------------------------------------------
__global__ void reset_kernel() {
    int i = blockIdx.x * 1024 + threadIdx.x;
    if (i < BATCH * NPOINTS) g_cent[i] = make_float4(0.f, 0.f, 0.f, 0.f);
}

// ---------------------------------------------------------------------------
// FPS role (blocks 0..7): selection math bit-identical to R7-R15, plus
// warp-level EXACT pruning:
//  - points binned into 8x8x8 Morton cells; warp w owns 256 compact points
//  - per-warp AABB; per step, conservative lb2 <= dist^2(c, box) via
//    round-DOWN arithmetic; warp skips its distance update iff
//    pd_max < lb2*0.99999f (proof: computed d >= true_d(1-8eps) > pd_max,
//    so fmin provably leaves every pd unchanged; cached warp key reused).
// ---------------------------------------------------------------------------
__device__ void fps_role(const float* __restrict__ xyz, float* __restrict__ new_xyz,
                         int b, int tid, float* dynsmem) {
    const int lane = tid & 31;
    const int warp = tid >> 5;
    const float* base = xyz + (size_t)b * NPTS * 3;

    float4* staging = (float4*)dynsmem;                   // 4096 * 16B
    int*    hist    = (int*)(dynsmem + NPTS * 4);         // 512
    int*    scanb   = hist + 512;                         // 512

    // ---- 1) histogram over Morton cells ----
    if (tid < 512) hist[tid] = 0;
    __syncthreads();
    int   mycell[8];
    float myx[8], myy[8], myz[8];
#pragma unroll
    for (int p = 0; p < 8; ++p) {
        int n = tid + p * 512;
        float x = base[n * 3 + 0], y = base[n * 3 + 1], z = base[n * 3 + 2];
        myx[p] = x; myy[p] = y; myz[p] = z;
        int ix = min(7, (int)(x * 8.0f));
        int iy = min(7, (int)(y * 8.0f));
        int iz = min(7, (int)(z * 8.0f));
        int m = spread3(ix) | (spread3(iy) << 1) | (spread3(iz) << 2);
        mycell[p] = m;
        atomicAdd(&hist[m], 1);
    }
    __syncthreads();

    // ---- 2) exclusive scan (512 cells, 512 threads, Hillis-Steele) ----
    {
        int v = hist[tid];
        int acc = v;
        scanb[tid] = acc;
        __syncthreads();
        for (int off = 1; off < 512; off <<= 1) {
            int t = (tid >= off) ? scanb[tid - off] : 0;
            __syncthreads();
            acc += t;
            scanb[tid] = acc;
            __syncthreads();
        }
        hist[tid] = acc - v;   // exclusive offset; reused as running cursor
    }
    __syncthreads();

    // ---- 3) scatter points (coords + original index) ----
#pragma unroll
    for (int p = 0; p < 8; ++p) {
        int pos = atomicAdd(&hist[mycell[p]], 1);
        staging[pos] = make_float4(myx[p], myy[p], myz[p],
                                   __int_as_float(tid + p * 512));
    }
    __syncthreads();

    // ---- 4) reload warp-contiguous points; pack pairs (k, k+4) negated ----
    float px[8], py[8], pz[8], pd[8];
    int   pn[8];
#pragma unroll
    for (int k = 0; k < 8; ++k) {
        float4 f = staging[warp * 256 + k * 32 + lane];
        px[k] = f.x; py[k] = f.y; pz[k] = f.z;
        pn[k] = __float_as_int(f.w);
        pd[k] = 1e10f;
    }
    unsigned long long pxp[4], pyp[4], pzp[4];
#pragma unroll
    for (int k = 0; k < 4; ++k) {
        pxp[k] = f2_pack(-px[k], -px[k + 4]);
        pyp[k] = f2_pack(-py[k], -py[k + 4]);
        pzp[k] = f2_pack(-pz[k], -pz[k + 4]);
    }

    // ---- 5) per-warp AABB (coords >= 0 -> uint order == float order) ----
    float lminx = px[0], lmaxx = px[0], lminy = py[0], lmaxy = py[0];
    float lminz = pz[0], lmaxz = pz[0];
#pragma unroll
    for (int k = 1; k < 8; ++k) {
        lminx = fminf(lminx, px[k]); lmaxx = fmaxf(lmaxx, px[k]);
        lminy = fminf(lminy, py[k]); lmaxy = fmaxf(lmaxy, py[k]);
        lminz = fminf(lminz, pz[k]); lmaxz = fmaxf(lmaxz, pz[k]);
    }
    const float bxmin = __uint_as_float(__reduce_min_sync(0xffffffffu, __float_as_uint(lminx)));
    const float bxmax = __uint_as_float(__reduce_max_sync(0xffffffffu, __float_as_uint(lmaxx)));
    const float bymin = __uint_as_float(__reduce_min_sync(0xffffffffu, __float_as_uint(lminy)));
    const float bymax = __uint_as_float(__reduce_max_sync(0xffffffffu, __float_as_uint(lmaxy)));
    const float bzmin = __uint_as_float(__reduce_min_sync(0xffffffffu, __float_as_uint(lminz)));
    const float bzmax = __uint_as_float(__reduce_max_sync(0xffffffffu, __float_as_uint(lmaxz)));

    __shared__ uint2 sWarp[32];   // ping-pong banks of 16

    float cx = __ldg(base + 0), cy = __ldg(base + 1), cz = __ldg(base + 2);
    if (tid == 0)
        stcg_v4(&g_cent[b * NPOINTS + 0], cx, cy, cz, __int_as_float(1));

    unsigned cwd = __float_as_uint(1e10f);  // cached warp key (never skips at t=1)
    unsigned cwi = 0;

    int bank = 0;
    for (int t = 1; t < NPOINTS; ++t) {
        // ---- conservative skip test (warp-uniform) ----
        float dxm = fmaxf(0.0f, fmaxf(__fsub_rd(bxmin, cx), __fsub_rd(cx, bxmax)));
        float dym = fmaxf(0.0f, fmaxf(__fsub_rd(bymin, cy), __fsub_rd(cy, bymax)));
        float dzm = fmaxf(0.0f, fmaxf(__fsub_rd(bzmin, cz), __fsub_rd(cz, bzmax)));
        float lb2 = __fadd_rd(__fadd_rd(__fmul_rd(dxm, dxm), __fmul_rd(dym, dym)),
                              __fmul_rd(dzm, dzm));
        const bool skip = (__uint_as_float(cwd) < lb2 * 0.99999f);

        if (!skip) {
            const unsigned long long cx2 = f2_pack(cx, cx);
            const unsigned long long cy2 = f2_pack(cy, cy);
            const unsigned long long cz2 = f2_pack(cz, cz);
#pragma unroll
            for (int p = 0; p < 4; ++p) {
                unsigned long long dx = f2_add(pxp[p], cx2);   // -(p-c): square equal
                unsigned long long dy = f2_add(pyp[p], cy2);
                unsigned long long dz = f2_add(pzp[p], cz2);
                unsigned long long s  = f2_add(f2_add(f2_mul(dx, dx), f2_mul(dy, dy)),
                                               f2_mul(dz, dz));
                float lo, hi;
                f2_unpack(s, lo, hi);
                pd[p]     = fminf(pd[p],     lo);
                pd[p + 4] = fminf(pd[p + 4], hi);
            }

            float m0 = fmaxf(pd[0], pd[1]);
            float m1 = fmaxf(pd[2], pd[3]);
            float m2 = fmaxf(pd[4], pd[5]);
            float m3 = fmaxf(pd[6], pd[7]);
            const float bd = fmaxf(fmaxf(m0, m1), fmaxf(m2, m3));

            int bi = 0x7fffffff;
#pragma unroll
            for (int p = 0; p < 8; ++p)
                bi = min(bi, (pd[p] == bd) ? pn[p] : 0x7fffffff);

            const unsigned bdb = __float_as_uint(bd);
            cwd = __reduce_max_sync(0xffffffffu, bdb);
            cwi = __reduce_min_sync(0xffffffffu,
                                    (bdb == cwd) ? (unsigned)bi : 0xffffffffu);
        }
        if (lane == 0) sWarp[bank * 16 + warp] = make_uint2(cwd, cwi);
        __syncthreads();

        const uint2 k  = sWarp[bank * 16 + (lane & 15)];
        const unsigned gd = __reduce_max_sync(0xffffffffu, k.x);
        const unsigned gi = __reduce_min_sync(0xffffffffu,
                                (k.x == gd) ? k.y : 0xffffffffu);
        const int idx = (int)gi;
        cx = __ldg(base + idx * 3 + 0);
        cy = __ldg(base + idx * 3 + 1);
        cz = __ldg(base + idx * 3 + 2);
        if (tid == 32)
            stcg_v4(&g_cent[b * NPOINTS + t], cx, cy, cz, __int_as_float(t + 1));
        bank ^= 1;
    }

    // final: materialize new_xyz from g_cent (once, off the serial path)
    for (int i = tid; i < NPOINTS; i += THREADS) {
        float4 cen = ldcg_v4(&g_cent[b * NPOINTS + i]);
        float* o = new_xyz + ((size_t)b * NPOINTS + i) * 3;
        o[0] = cen.x; o[1] = cen.y; o[2] = cen.z;
    }
}

// ---------------------------------------------------------------------------
// MLP building blocks (identical arithmetic to R8-R15)
// ---------------------------------------------------------------------------
template <int CIN, int COUT, int PIN>
__device__ __forceinline__ void gemm_acc(const float* in_s,
                                         const float* __restrict__ W,
                                         const float* __restrict__ bias,
                                         float acc[4][COUT / 16],
                                         int c, int r) {
    constexpr int JW = COUT / 16;
#pragma unroll
    for (int j = 0; j < JW; ++j) {
        float bj = __ldg(bias + c * JW + j);
#pragma unroll
        for (int m = 0; m < 4; ++m) acc[m][j] = bj;
    }

    const float* wbase = W + c * JW;
    constexpr int CMAIN = CIN & ~3;

    for (int i = 0; i < CMAIN; i += 4) {
        float4 a0 = *(const float4*)(in_s + (r + 0)  * PIN + i);
        float4 a1 = *(const float4*)(in_s + (r + 8)  * PIN + i);
        float4 a2 = *(const float4*)(in_s + (r + 16) * PIN + i);
        float4 a3 = *(const float4*)(in_s + (r + 24) * PIN + i);
        const float av[4][4] = {
            {a0.x, a1.x, a2.x, a3.x},
            {a0.y, a1.y, a2.y, a3.y},
            {a0.z, a1.z, a2.z, a3.z},
            {a0.w, a1.w, a2.w, a3.w}};
#pragma unroll
        for (int u = 0; u < 4; ++u) {
            const float4* wp = (const float4*)(wbase + (i + u) * COUT);
#pragma unroll
            for (int v = 0; v < JW / 4; ++v) {
                float4 w = __ldg(wp + v);
#pragma unroll
                for (int m = 0; m < 4; ++m) {
                    acc[m][v * 4 + 0] = fmaf(av[u][m], w.x, acc[m][v * 4 + 0]);
                    acc[m][v * 4 + 1] = fmaf(av[u][m], w.y, acc[m][v * 4 + 1]);
                    acc[m][v * 4 + 2] = fmaf(av[u][m], w.z, acc[m][v * 4 + 2]);
                    acc[m][v * 4 + 3] = fmaf(av[u][m], w.w, acc[m][v * 4 + 3]);
                }
            }
        }
    }
    for (int i = CMAIN; i < CIN; ++i) {
        float s0 = in_s[(r + 0)  * PIN + i];
        float s1 = in_s[(r + 8)  * PIN + i];
        float s2 = in_s[(r + 16) * PIN + i];
        float s3 = in_s[(r + 24) * PIN + i];
        const float4* wp = (const float4*)(wbase + i * COUT);
#pragma unroll
        for (int v = 0; v < JW / 4; ++v) {
            float4 w = __ldg(wp + v);
#pragma unroll
            for (int q = 0; q < 4; ++q) {
                acc[0][v * 4 + q] = fmaf(s0, ((const float*)&w)[q], acc[0][v * 4 + q]);
                acc[1][v * 4 + q] = fmaf(s1, ((const float*)&w)[q], acc[1][v * 4 + q]);
                acc[2][v * 4 + q] = fmaf(s2, ((const float*)&w)[q], acc[2][v * 4 + q]);
                acc[3][v * 4 + q] = fmaf(s3, ((const float*)&w)[q], acc[3][v * 4 + q]);
            }
        }
    }
}

template <int COUT>
__device__ __forceinline__ void ln_relu_reg(float acc[4][COUT / 16],
                                            const float* __restrict__ g,
                                            const float* __restrict__ be, int c) {
    constexpr int JW = COUT / 16;
    float gv[JW], bv[JW];
#pragma unroll
    for (int j = 0; j < JW; ++j) { gv[j] = __ldg(g + c * JW + j); bv[j] = __ldg(be + c * JW + j); }
#pragma unroll
    for (int m = 0; m < 4; ++m) {
        float sum = 0.0f;
#pragma unroll
        for (int j = 0; j < JW; ++j) sum += acc[m][j];
        sum += __shfl_xor_sync(0xffffffffu, sum, 1);
        sum += __shfl_xor_sync(0xffffffffu, sum, 2);
        sum += __shfl_xor_sync(0xffffffffu, sum, 4);
        sum += __shfl_xor_sync(0xffffffffu, sum, 8);
        const float mu = sum * (1.0f / COUT);
        float sq = 0.0f;
#pragma unroll
        for (int j = 0; j < JW; ++j) { float d = acc[m][j] - mu; sq += d * d; }
        sq += __shfl_xor_sync(0xffffffffu, sq, 1);
        sq += __shfl_xor_sync(0xffffffffu, sq, 2);
        sq += __shfl_xor_sync(0xffffffffu, sq, 4);
        sq += __shfl_xor_sync(0xffffffffu, sq, 8);
        const float inv = rsqrtf(sq * (1.0f / COUT) + 1e-5f);
#pragma unroll
        for (int j = 0; j < JW; ++j)
            acc[m][j] = fmaxf((acc[m][j] - mu) * inv * gv[j] + bv[j], 0.0f);
    }
}

template <int COUT, int POUT>
__device__ __forceinline__ void store_rows(const float acc[4][COUT / 16],
                                           float* out_s, int c, int r) {
    constexpr int JW = COUT / 16;
#pragma unroll
    for (int m = 0; m < 4; ++m)
#pragma unroll
        for (int v = 0; v < JW / 4; ++v)
            *(float4*)(out_s + (r + 8 * m) * POUT + c * JW + v * 4) =
                make_float4(acc[m][v * 4 + 0], acc[m][v * 4 + 1],
                            acc[m][v * 4 + 2], acc[m][v * 4 + 3]);
}

// ---------------------------------------------------------------------------
// Worker role: NGRP groups of 128 threads, decoupled via named barriers.
// ---------------------------------------------------------------------------
__device__ void worker_role(const float* __restrict__ xyz,
                            const float* __restrict__ points,
                            const float* __restrict__ W1, const float* __restrict__ b1,
                            const float* __restrict__ g1, const float* __restrict__ be1,
                            const float* __restrict__ W2, const float* __restrict__ b2,
                            const float* __restrict__ g2, const float* __restrict__ be2,
                            const float* __restrict__ W3, const float* __restrict__ b3,
                            const float* __restrict__ g3, const float* __restrict__ be3,
                            float* __restrict__ new_points,
                            float* smem, int wb, int tid) {
    const int b = wb % BATCH;
    const int w = wb / BATCH;
    const int grp  = tid >> 7;
    const int gtid = tid & 127;
    const int c = gtid & 15;
    const int r = gtid >> 4;
    const int bid = grp + 1;

    float* sxyz = smem;
    float* gbase = smem + SXYZ_F + grp * GRP_F;
    float* bufA  = gbase;
    float* bufB  = gbase + 32 * PIN_A;
    int*   sIdx  = (int*)(smem + SXYZ_F + NGRP * GRP_F) + grp * 32;
    float* sCen  = (float*)((int*)(smem + SXYZ_F + NGRP * GRP_F) + NGRP * 32) + grp * 4;

    {
        const float4* src = (const float4*)(xyz + (size_t)b * NPTS * 3);
        for (int i = tid; i < SXYZ_F / 4; i += THREADS)
            ((float4*)sxyz)[i] = src[i];
    }
    __syncthreads();

    for (int base = w * NGRP; base < NPOINTS; base += NW_PER_B * NGRP) {
        const int s = base + grp;

        if (gtid == 0) {
            const float4* cp = &g_cent[b * NPOINTS + s];
            float4 cen = ldcg_v4(cp);
            while (__float_as_int(cen.w) != s + 1) {
                __nanosleep(80);
                cen = ldcg_v4(cp);
            }
            sCen[0] = cen.x; sCen[1] = cen.y; sCen[2] = cen.z;
        }
        bar_grp(bid);

        if (gtid < 32) {
            const int lane = gtid;
            const float cx = sCen[0], cy = sCen[1], cz = sCen[2];
            const float R2 = (float)(0.2 * 0.2);
            int cnt = 0, first = -1;
            for (int rr = 0; rr < NPTS / 32; ++rr) {
                int n = rr * 32 + lane;
                float d = sqd_nofma(sxyz[n * 3], sxyz[n * 3 + 1], sxyz[n * 3 + 2],
                                    cx, cy, cz);
                bool ok = !(d > R2);
                unsigned m = __ballot_sync(0xffffffffu, ok);
                if (first < 0 && m) first = rr * 32 + (__ffs(m) - 1);
                if (ok) {
                    int pos = cnt + __popc(m & ((1u << lane) - 1u));
                    if (pos < NSAMPLE) sIdx[pos] = n;
                }
                cnt += __popc(m);
                if (cnt >= NSAMPLE) break;
            }
            if (cnt < NSAMPLE && lane >= cnt && lane < NSAMPLE) sIdx[lane] = first;
        }
        bar_grp(bid);

        {
            const int k = gtid >> 2, q = gtid & 3;
            const int n = sIdx[k];
            const float4* prow = (const float4*)(points + ((size_t)b * NPTS + n) * 64) + q * 4;
            float* dst = bufA + k * PIN_A + 3 + q * 16;
#pragma unroll
            for (int v = 0; v < 4; ++v) {
                float4 f = __ldg(prow + v);
                dst[v * 4 + 0] = f.x;
                dst[v * 4 + 1] = f.y;
                dst[v * 4 + 2] = f.z;
                dst[v * 4 + 3] = f.w;
            }
            if (q == 0) {
                bufA[k * PIN_A + 0] = sxyz[n * 3 + 0] - sCen[0];
                bufA[k * PIN_A + 1] = sxyz[n * 3 + 1] - sCen[1];
                bufA[k * PIN_A + 2] = sxyz[n * 3 + 2] - sCen[2];
            }
        }
        bar_grp(bid);

        {   // layer 1: 67 -> 64
            float acc[4][4];
            gemm_acc<67, 64, PIN_A>(bufA, W1, b1, acc, c, r);
            ln_relu_reg<64>(acc, g1, be1, c);
            store_rows<64, PIN_B>(acc, bufB, c, r);
        }
        bar_grp(bid);

        {   // layer 2: 64 -> 64
            float acc[4][4];
            gemm_acc<64, 64, PIN_B>(bufB, W2, b2, acc, c, r);
            ln_relu_reg<64>(acc, g2, be2, c);
            store_rows<64, PIN_A>(acc, bufA, c, r);
        }
        bar_grp(bid);

        {   // layer 3: 64 -> 128, fused partial max over 4 samples
            float acc[4][8];
            gemm_acc<64, 128, PIN_A>(bufA, W3, b3, acc, c, r);
            ln_relu_reg<128>(acc, g3, be3, c);
#pragma unroll
            for (int j = 0; j < 8; ++j) {
                float pm = fmaxf(fmaxf(acc[0][j], acc[1][j]), fmaxf(acc[2][j], acc[3][j]));
                bufB[r * PIN_B + c * 8 + j] = pm;
            }
        }
        bar_grp(bid);

        {
            float m = 0.0f;
#pragma unroll
            for (int k = 0; k < 8; ++k) m = fmaxf(m, bufB[k * PIN_B + gtid]);
            new_points[((size_t)b * NPOINTS + s) * 128 + gtid] = m;
        }
        bar_grp(bid);
    }
}

// ---------------------------------------------------------------------------
__global__ __launch_bounds__(THREADS, 1) void fused_kernel(
    const float* __restrict__ xyz, const float* __restrict__ points,
    const float* __restrict__ W1, const float* __restrict__ b1,
    const float* __restrict__ g1, const float* __restrict__ be1,
    const float* __restrict__ W2, const float* __restrict__ b2,
    const float* __restrict__ g2, const float* __restrict__ be2,
    const float* __restrict__ W3, const float* __restrict__ b3,
    const float* __restrict__ g3, const float* __restrict__ be3,
    float* __restrict__ new_xyz, float* __restrict__ new_points) {
    extern __shared__ float smem[];
    const int tid = threadIdx.x;
    if (blockIdx.x < BATCH) {
        fps_role(xyz, new_xyz, blockIdx.x, tid, smem);
    } else {
        worker_role(xyz, points,
                    W1, b1, g1, be1, W2, b2, g2, be2, W3, b3, g3, be3,
                    new_points, smem, blockIdx.x - BATCH, tid);
    }
}

// ---------------------------------------------------------------------------
extern "C" void kernel_launch(void* const* d_in, const int* in_sizes, int n_in,
                              void* d_out, int out_size) {
    (void)in_sizes; (void)n_in; (void)out_size;
    const float* xyz    = (const float*)d_in[0];
    const float* points = (const float*)d_in[1];
    const float* W1  = (const float*)d_in[2];
    const float* b1  = (const float*)d_in[3];
    const float* g1  = (const float*)d_in[4];
    const float* be1 = (const float*)d_in[5];
    const float* W2  = (const float*)d_in[6];
    const float* b2  = (const float*)d_in[7];
    const float* g2  = (const float*)d_in[8];
    const float* be2 = (const float*)d_in[9];
    const float* W3  = (const float*)d_in[10];
    const float* b3  = (const float*)d_in[11];
    const float* g3  = (const float*)d_in[12];
    const float* be3 = (const float*)d_in[13];

    float* out        = (float*)d_out;
    float* new_xyz    = out;                          // [8,1024,3]
    float* new_points = out + BATCH * NPOINTS * 3;    // [8,1024,128]

    cudaFuncSetAttribute(fused_kernel, cudaFuncAttributeMaxDynamicSharedMemorySize,
                         SMEM_DYN);

    reset_kernel<<<BATCH, 1024>>>();
    fused_kernel<<<NBLOCKS, THREADS, SMEM_DYN>>>(xyz, points,
                                                 W1, b1, g1, be1,
                                                 W2, b2, g2, be2,
                                                 W3, b3, g3, be3,
                                                 new_xyz, new_points);
}